// round 1
// baseline (speedup 1.0000x reference)
#include <cuda_runtime.h>
#include <math.h>

#define B   4
#define S   1024
#define HID 1024
#define NH  16
#define NKV 4
#define DH  64

// Scratch (allocation-free rule: __device__ globals)
__device__ float g_Q[B*S*NH*DH];    // [b, s, h, dh]  16 MB
__device__ float g_K[B*S*NKV*DH];   // [b, s, hkv, dh] 4 MB
__device__ float g_V[B*S*NKV*DH];   // 4 MB
__device__ float g_A[B*S*NH*DH];    // attention out, [b, s, h, dh] 16 MB

// ---------------------------------------------------------------------------
// Generic fp32 GEMM: C[M,N] = A[M,K] @ B[K,N], row-major, tiles 64x64x16,
// 256 threads, 4x4 per-thread microtile. M%64==0, N%64==0, K%16==0 assumed.
// ---------------------------------------------------------------------------
__global__ void gemm64(const float* __restrict__ A, const float* __restrict__ Bm,
                       float* __restrict__ C, int M, int N, int K)
{
    __shared__ float As[16][68];   // [k][m] transposed, padded
    __shared__ float Bs[16][68];   // [k][n], padded (float4-aligned offsets)

    const int tid = threadIdx.x;
    const int tx = tid & 15, ty = tid >> 4;
    const int m0 = blockIdx.y * 64, n0 = blockIdx.x * 64;

    const int ar = tid >> 2,  ac = (tid & 3) << 2;   // A: row 0..63, col4
    const int br = tid >> 4,  bc = (tid & 15) << 2;  // B: row 0..15, col4

    const float* Ap = A + (size_t)(m0 + ar) * K + ac;
    const float* Bp = Bm + (size_t)br * N + n0 + bc;

    float acc[4][4] = {};

    for (int k0 = 0; k0 < K; k0 += 16) {
        float4 av = *(const float4*)(Ap + k0);
        float4 bv = *(const float4*)(Bp + (size_t)k0 * N);
        As[ac+0][ar] = av.x; As[ac+1][ar] = av.y;
        As[ac+2][ar] = av.z; As[ac+3][ar] = av.w;
        *(float4*)&Bs[br][bc] = bv;
        __syncthreads();

        #pragma unroll
        for (int kk = 0; kk < 16; kk++) {
            float a[4], b[4];
            #pragma unroll
            for (int i = 0; i < 4; i++) a[i] = As[kk][ty*4 + i];
            #pragma unroll
            for (int j = 0; j < 4; j++) b[j] = Bs[kk][tx*4 + j];
            #pragma unroll
            for (int i = 0; i < 4; i++)
                #pragma unroll
                for (int j = 0; j < 4; j++)
                    acc[i][j] = fmaf(a[i], b[j], acc[i][j]);
        }
        __syncthreads();
    }

    #pragma unroll
    for (int i = 0; i < 4; i++)
        #pragma unroll
        for (int j = 0; j < 4; j++)
            C[(size_t)(m0 + ty*4 + i) * N + n0 + tx*4 + j] = acc[i][j];
}

// ---------------------------------------------------------------------------
// Flash-attention style fused kernel. One CTA = (b, h, 64-query tile).
// S = Q K^T * 0.125 + bias; mask==0 -> -1e9; online softmax; O += P V.
// 256 threads (16x16); each thread owns 4 q-rows x 4 cols.
// Dynamic smem: Qs/Ks/Vs/Ss each 64x65 + stats.
// ---------------------------------------------------------------------------
__global__ void attn_kernel(const float* __restrict__ bias,
                            const int*   __restrict__ mask)
{
    extern __shared__ float sm[];
    const int ST = 65;
    float* Qs  = sm;
    float* Ks  = Qs + 64*ST;
    float* Vs  = Ks + 64*ST;
    float* Ss  = Vs + 64*ST;
    float* m_s = Ss + 64*ST;
    float* l_s = m_s + 64;
    float* al_s= l_s + 64;

    const int tid = threadIdx.x;
    const int tx = tid & 15, ty = tid >> 4;
    const int qt = blockIdx.x, h = blockIdx.y, bb = blockIdx.z;
    const int hkv = h >> 2;   // repeat_interleave: kv head = h / (H/HKV)

    // Load Q tile [64 q x 64 d]
    {
        const int r0 = tid >> 4, d = (tid & 15) << 2;
        #pragma unroll
        for (int it = 0; it < 4; it++) {
            int r = r0 + it*16;
            int q = qt*64 + r;
            float4 v = *(const float4*)&g_Q[(size_t)(bb*S + q)*(NH*DH) + h*DH + d];
            Qs[r*ST+d]   = v.x; Qs[r*ST+d+1] = v.y;
            Qs[r*ST+d+2] = v.z; Qs[r*ST+d+3] = v.w;
        }
    }
    if (tid < 64) { m_s[tid] = -INFINITY; l_s[tid] = 0.f; }

    float o[4][4] = {};
    const float scale = 0.125f;   // 1/sqrt(64)

    for (int kt = 0; kt < S/64; kt++) {
        __syncthreads();   // protect Ks/Vs/Ss of previous iteration
        // Load K,V tiles [64 k x 64 d]
        {
            const int r0 = tid >> 4, d = (tid & 15) << 2;
            #pragma unroll
            for (int it = 0; it < 4; it++) {
                int r = r0 + it*16;
                int krow = kt*64 + r;
                size_t base = (size_t)(bb*S + krow)*(NKV*DH) + hkv*DH + d;
                float4 kv = *(const float4*)&g_K[base];
                Ks[r*ST+d]   = kv.x; Ks[r*ST+d+1] = kv.y;
                Ks[r*ST+d+2] = kv.z; Ks[r*ST+d+3] = kv.w;
                float4 vv = *(const float4*)&g_V[base];
                Vs[r*ST+d]   = vv.x; Vs[r*ST+d+1] = vv.y;
                Vs[r*ST+d+2] = vv.z; Vs[r*ST+d+3] = vv.w;
            }
        }
        __syncthreads();

        // S = Q K^T (4x4 microtile per thread)
        float sr[4][4] = {};
        #pragma unroll 8
        for (int d = 0; d < 64; d++) {
            float a[4], bk[4];
            #pragma unroll
            for (int i = 0; i < 4; i++) a[i] = Qs[(ty*4+i)*ST + d];
            #pragma unroll
            for (int j = 0; j < 4; j++) bk[j] = Ks[(tx*4+j)*ST + d];
            #pragma unroll
            for (int i = 0; i < 4; i++)
                #pragma unroll
                for (int j = 0; j < 4; j++)
                    sr[i][j] = fmaf(a[i], bk[j], sr[i][j]);
        }

        // scale + bias + mask -> Ss
        {
            size_t boff = ((size_t)(bb*NH + h)*S + qt*64)*S + kt*64;
            size_t moff = ((size_t)bb*S + qt*64)*S + kt*64;
            #pragma unroll
            for (int i = 0; i < 4; i++) {
                int ql = ty*4 + i;
                float4 b4 = *(const float4*)&bias[boff + (size_t)ql*S + tx*4];
                int4   m4 = *(const int4*)  &mask[moff + (size_t)ql*S + tx*4];
                float s0 = fmaf(sr[i][0], scale, b4.x); if (m4.x == 0) s0 = -1e9f;
                float s1 = fmaf(sr[i][1], scale, b4.y); if (m4.y == 0) s1 = -1e9f;
                float s2 = fmaf(sr[i][2], scale, b4.z); if (m4.z == 0) s2 = -1e9f;
                float s3 = fmaf(sr[i][3], scale, b4.w); if (m4.w == 0) s3 = -1e9f;
                Ss[ql*ST + tx*4+0] = s0; Ss[ql*ST + tx*4+1] = s1;
                Ss[ql*ST + tx*4+2] = s2; Ss[ql*ST + tx*4+3] = s3;
            }
        }
        __syncthreads();

        // Online softmax stats: 4 threads per row (same warp), 16 cols each
        {
            int row = tid >> 2, part = tid & 3;
            float* srow = Ss + row*ST + part*16;
            float tmax = -INFINITY;
            #pragma unroll
            for (int c = 0; c < 16; c++) tmax = fmaxf(tmax, srow[c]);
            tmax = fmaxf(tmax, __shfl_xor_sync(0xffffffffu, tmax, 1));
            tmax = fmaxf(tmax, __shfl_xor_sync(0xffffffffu, tmax, 2));
            float mo = m_s[row];
            float mn = fmaxf(mo, tmax);
            float tsum = 0.f;
            #pragma unroll
            for (int c = 0; c < 16; c++) {
                float p = __expf(srow[c] - mn);
                srow[c] = p;
                tsum += p;
            }
            tsum += __shfl_xor_sync(0xffffffffu, tsum, 1);
            tsum += __shfl_xor_sync(0xffffffffu, tsum, 2);
            if (part == 0) {
                float alpha = __expf(mo - mn);   // 0 on first tile (mo=-inf)
                al_s[row] = alpha;
                l_s[row]  = l_s[row]*alpha + tsum;
                m_s[row]  = mn;
            }
        }
        __syncthreads();

        // Rescale O and accumulate P @ V
        {
            float al[4];
            #pragma unroll
            for (int i = 0; i < 4; i++) al[i] = al_s[ty*4+i];
            #pragma unroll
            for (int i = 0; i < 4; i++)
                #pragma unroll
                for (int j = 0; j < 4; j++) o[i][j] *= al[i];

            #pragma unroll 8
            for (int kk = 0; kk < 64; kk++) {
                float p[4], vv[4];
                #pragma unroll
                for (int i = 0; i < 4; i++) p[i]  = Ss[(ty*4+i)*ST + kk];
                #pragma unroll
                for (int j = 0; j < 4; j++) vv[j] = Vs[kk*ST + tx*4 + j];
                #pragma unroll
                for (int i = 0; i < 4; i++)
                    #pragma unroll
                    for (int j = 0; j < 4; j++)
                        o[i][j] = fmaf(p[i], vv[j], o[i][j]);
            }
        }
    }
    __syncthreads();

    // Normalize and write [b, s, h, dh]
    #pragma unroll
    for (int i = 0; i < 4; i++) {
        int ql = ty*4 + i;
        float inv = 1.0f / l_s[ql];
        size_t base = (size_t)(bb*S + qt*64 + ql)*(NH*DH) + h*DH + tx*4;
        g_A[base+0] = o[i][0]*inv;
        g_A[base+1] = o[i][1]*inv;
        g_A[base+2] = o[i][2]*inv;
        g_A[base+3] = o[i][3]*inv;
    }
}

// ---------------------------------------------------------------------------
extern "C" void kernel_launch(void* const* d_in, const int* in_sizes, int n_in,
                              void* d_out, int out_size)
{
    const float* X    = (const float*)d_in[0];   // hidden_states [4,1024,1024]
    const float* bias = (const float*)d_in[1];   // [4,16,1024,1024]
    const int*   mask = (const int*  )d_in[2];   // [4,1,1024,1024]
    const float* Wq   = (const float*)d_in[3];   // [1024,1024]
    const float* Wk   = (const float*)d_in[4];   // [1024,256]
    const float* Wv   = (const float*)d_in[5];   // [1024,256]
    const float* Wo   = (const float*)d_in[6];   // [1024,1024]
    float* out = (float*)d_out;

    float *pQ, *pK, *pV, *pA;
    cudaGetSymbolAddress((void**)&pQ, g_Q);
    cudaGetSymbolAddress((void**)&pK, g_K);
    cudaGetSymbolAddress((void**)&pV, g_V);
    cudaGetSymbolAddress((void**)&pA, g_A);

    dim3 blk(256);

    // Projections
    gemm64<<<dim3((NH*DH)/64,  (B*S)/64), blk>>>(X, Wq, pQ, B*S, NH*DH,  HID);
    gemm64<<<dim3((NKV*DH)/64, (B*S)/64), blk>>>(X, Wk, pK, B*S, NKV*DH, HID);
    gemm64<<<dim3((NKV*DH)/64, (B*S)/64), blk>>>(X, Wv, pV, B*S, NKV*DH, HID);

    // Fused attention
    int smem = (4*64*65 + 3*64) * (int)sizeof(float);   // 67,328 B
    cudaFuncSetAttribute(attn_kernel, cudaFuncAttributeMaxDynamicSharedMemorySize, smem);
    attn_kernel<<<dim3(S/64, NH, B), blk, smem>>>(bias, mask);

    // Output projection
    gemm64<<<dim3(HID/64, (B*S)/64), blk>>>(pA, Wo, out, B*S, HID, HID);
}

// round 3
// speedup vs baseline: 1.0251x; 1.0251x over previous
#include <cuda_runtime.h>
#include <cuda_bf16.h>
#include <math.h>
#include <stdint.h>

#define B   4
#define S   1024
#define HID 1024
#define NH  16
#define NKV 4
#define DH  64

// ---------------------------------------------------------------------------
// Scratch (allocation-free rule: __device__ globals)
// ---------------------------------------------------------------------------
__device__ float g_Q[B*S*NH*DH];
__device__ float g_K[B*S*NKV*DH];
__device__ float g_V[B*S*NKV*DH];
__device__ float g_A[B*S*NH*DH];

__device__ __nv_bfloat16 g_Xhi[B*S*HID], g_Xlo[B*S*HID];
__device__ __nv_bfloat16 g_Ahi[B*S*HID], g_Alo[B*S*HID];
__device__ __nv_bfloat16 g_WqThi[HID*NH*DH],  g_WqTlo[HID*NH*DH];
__device__ __nv_bfloat16 g_WkThi[HID*NKV*DH], g_WkTlo[HID*NKV*DH];
__device__ __nv_bfloat16 g_WvThi[HID*NKV*DH], g_WvTlo[HID*NKV*DH];
__device__ __nv_bfloat16 g_WoThi[HID*HID],    g_WoTlo[HID*HID];

// ---------------------------------------------------------------------------
// mma.sync helpers (baseline PTX — safe on sm_103 family targets)
// ---------------------------------------------------------------------------
__device__ __forceinline__ uint32_t smem_u32(const void* p) {
    uint32_t a;
    asm("{ .reg .u64 t; cvta.to.shared.u64 t, %1; cvt.u32.u64 %0, t; }" : "=r"(a) : "l"(p));
    return a;
}
__device__ __forceinline__ void ldmx4(uint32_t* r, uint32_t addr) {
    asm volatile("ldmatrix.sync.aligned.m8n8.x4.shared.b16 {%0,%1,%2,%3}, [%4];"
                 : "=r"(r[0]), "=r"(r[1]), "=r"(r[2]), "=r"(r[3]) : "r"(addr));
}
__device__ __forceinline__ void mma16816(float* d, const uint32_t* a, const uint32_t* b) {
    asm volatile("mma.sync.aligned.m16n8k16.row.col.f32.bf16.bf16.f32 "
                 "{%0,%1,%2,%3}, {%4,%5,%6,%7}, {%8,%9}, {%0,%1,%2,%3};"
                 : "+f"(d[0]), "+f"(d[1]), "+f"(d[2]), "+f"(d[3])
                 : "r"(a[0]), "r"(a[1]), "r"(a[2]), "r"(a[3]), "r"(b[0]), "r"(b[1]));
}

// ---------------------------------------------------------------------------
// fp32 -> (bf16 hi, bf16 lo) split
// ---------------------------------------------------------------------------
__global__ void split_kernel(const float* __restrict__ x,
                             __nv_bfloat16* __restrict__ hi,
                             __nv_bfloat16* __restrict__ lo, int n4)
{
    int i = blockIdx.x * 256 + threadIdx.x;
    if (i >= n4) return;
    float4 v = ((const float4*)x)[i];
    __nv_bfloat16 h0 = __float2bfloat16(v.x), h1 = __float2bfloat16(v.y);
    __nv_bfloat16 h2 = __float2bfloat16(v.z), h3 = __float2bfloat16(v.w);
    __nv_bfloat16 l0 = __float2bfloat16(v.x - __bfloat162float(h0));
    __nv_bfloat16 l1 = __float2bfloat16(v.y - __bfloat162float(h1));
    __nv_bfloat16 l2 = __float2bfloat16(v.z - __bfloat162float(h2));
    __nv_bfloat16 l3 = __float2bfloat16(v.w - __bfloat162float(h3));
    ((__nv_bfloat162*)hi)[2*i]   = __nv_bfloat162(h0, h1);
    ((__nv_bfloat162*)hi)[2*i+1] = __nv_bfloat162(h2, h3);
    ((__nv_bfloat162*)lo)[2*i]   = __nv_bfloat162(l0, l1);
    ((__nv_bfloat162*)lo)[2*i+1] = __nv_bfloat162(l2, l3);
}

// W [K,N] fp32 -> W^T [N,K] bf16 hi/lo
__global__ void transpose_split(const float* __restrict__ W,
                                __nv_bfloat16* __restrict__ hiT,
                                __nv_bfloat16* __restrict__ loT, int K, int N)
{
    __shared__ float t[32][33];
    int n0 = blockIdx.x * 32, k0 = blockIdx.y * 32;
    int tx = threadIdx.x, ty = threadIdx.y;
    #pragma unroll
    for (int i = 0; i < 32; i += 8)
        t[ty + i][tx] = W[(size_t)(k0 + ty + i) * N + n0 + tx];
    __syncthreads();
    #pragma unroll
    for (int i = 0; i < 32; i += 8) {
        float v = t[tx][ty + i];
        __nv_bfloat16 h = __float2bfloat16(v);
        size_t o = (size_t)(n0 + ty + i) * K + k0 + tx;
        hiT[o] = h;
        loT[o] = __float2bfloat16(v - __bfloat162float(h));
    }
}

// ---------------------------------------------------------------------------
// mma.sync split-bf16 GEMM: C[M,N] = A[M,K] @ B^T  (B given as [N,K])
// CTA 128x128, K-chunk 32, 8 warps in 4(m) x 2(n); warp tile 32x64.
// ---------------------------------------------------------------------------
#define KC   32
#define ASTR 40   // smem row stride in bf16 elems (80B, 16B-aligned)

__global__ void __launch_bounds__(256)
gemm_mma(const __nv_bfloat16* __restrict__ Ahi, const __nv_bfloat16* __restrict__ Alo,
         const __nv_bfloat16* __restrict__ Bhi, const __nv_bfloat16* __restrict__ Blo,
         float* __restrict__ C, int M, int N, int K)
{
    __shared__ __nv_bfloat16 sA[2][128][ASTR];   // [hi/lo][row][k]
    __shared__ __nv_bfloat16 sB[2][128][ASTR];

    const int tid = threadIdx.x, wid = tid >> 5, lane = tid & 31;
    const int wm = (wid & 3) * 32;    // warp m offset in tile
    const int wn = (wid >> 2) * 64;   // warp n offset
    const int m0 = blockIdx.y * 128, n0 = blockIdx.x * 128;

    // loader: each thread covers row (tid>>1), 2 uint4 (16 bf16) per tile
    const int ldr = tid >> 1;
    const int ldc = (tid & 1) * 16;

    // ldmatrix lane addresses (element offsets within a [128][ASTR] tile)
    // A fragment (m16k16): lanes 0-15 rows 0-15 @ col0; 16-31 rows 0-15 @ col8
    const int a_row = (lane & 15), a_col = (lane >> 4) * 8;
    // B fragment pair (two n8 tiles): 0-7:n0-7@k0  8-15:n0-7@k8  16-23:n8-15@k0  24-31:n8-15@k8
    const int b_row = (lane & 7) + ((lane >> 4) << 3), b_col = ((lane >> 3) & 1) * 8;

    const uint32_t sAh = smem_u32(&sA[0][0][0]), sAl = smem_u32(&sA[1][0][0]);
    const uint32_t sBh = smem_u32(&sB[0][0][0]), sBl = smem_u32(&sB[1][0][0]);

    float acc[2][8][4] = {};   // [m16 tile][n8 tile][frag]

    for (int k0 = 0; k0 < K; k0 += KC) {
        // load 4 tiles (A hi/lo 128x32, B hi/lo 128x32)
        {
            size_t ga = (size_t)(m0 + ldr) * K + k0 + ldc;
            size_t gb = (size_t)(n0 + ldr) * K + k0 + ldc;
            *(uint4*)&sA[0][ldr][ldc]     = *(const uint4*)(Ahi + ga);
            *(uint4*)&sA[0][ldr][ldc + 8] = *(const uint4*)(Ahi + ga + 8);
            *(uint4*)&sA[1][ldr][ldc]     = *(const uint4*)(Alo + ga);
            *(uint4*)&sA[1][ldr][ldc + 8] = *(const uint4*)(Alo + ga + 8);
            *(uint4*)&sB[0][ldr][ldc]     = *(const uint4*)(Bhi + gb);
            *(uint4*)&sB[0][ldr][ldc + 8] = *(const uint4*)(Bhi + gb + 8);
            *(uint4*)&sB[1][ldr][ldc]     = *(const uint4*)(Blo + gb);
            *(uint4*)&sB[1][ldr][ldc + 8] = *(const uint4*)(Blo + gb + 8);
        }
        __syncthreads();

        #pragma unroll
        for (int kk = 0; kk < KC; kk += 16) {
            uint32_t ahi[2][4], alo[2][4], bhi[4][4], blo[4][4];
            #pragma unroll
            for (int mi = 0; mi < 2; mi++) {
                uint32_t off = ((wm + mi * 16 + a_row) * ASTR + kk + a_col) * 2;
                ldmx4(ahi[mi], sAh + off);
                ldmx4(alo[mi], sAl + off);
            }
            #pragma unroll
            for (int t = 0; t < 4; t++) {
                uint32_t off = ((wn + t * 16 + b_row) * ASTR + kk + b_col) * 2;
                ldmx4(bhi[t], sBh + off);
                ldmx4(blo[t], sBl + off);
            }
            #pragma unroll
            for (int mi = 0; mi < 2; mi++)
                #pragma unroll
                for (int nj = 0; nj < 8; nj++) {
                    const uint32_t* bh = &bhi[nj >> 1][(nj & 1) * 2];
                    const uint32_t* bl = &blo[nj >> 1][(nj & 1) * 2];
                    mma16816(acc[mi][nj], ahi[mi], bh);   // hi*hi
                    mma16816(acc[mi][nj], ahi[mi], bl);   // hi*lo
                    mma16816(acc[mi][nj], alo[mi], bh);   // lo*hi
                }
        }
        __syncthreads();
    }

    // epilogue: direct fp32 stores (2 floats per frag-half)
    #pragma unroll
    for (int mi = 0; mi < 2; mi++) {
        int row = m0 + wm + mi * 16 + (lane >> 2);
        #pragma unroll
        for (int nj = 0; nj < 8; nj++) {
            int col = n0 + wn + nj * 8 + (lane & 3) * 2;
            *(float2*)&C[(size_t)row * N + col]       = make_float2(acc[mi][nj][0], acc[mi][nj][1]);
            *(float2*)&C[(size_t)(row + 8) * N + col] = make_float2(acc[mi][nj][2], acc[mi][nj][3]);
        }
    }
}

// ---------------------------------------------------------------------------
// Flash-attention (CUDA cores, LDS.128-vectorized)
// ---------------------------------------------------------------------------
#define ST 68   // row stride in floats (272B, 16B multiple)

__global__ void attn_kernel(const float* __restrict__ bias,
                            const int*   __restrict__ mask)
{
    extern __shared__ float smf[];
    float* Qs  = smf;
    float* Ks  = Qs + 64 * ST;
    float* Vs  = Ks + 64 * ST;
    float* Ss  = Vs + 64 * ST;
    float* m_s = Ss + 64 * ST;
    float* l_s = m_s + 64;
    float* al_s = l_s + 64;

    const int tid = threadIdx.x;
    const int tx = tid & 15, ty = tid >> 4;
    const int qt = blockIdx.x, h = blockIdx.y, bb = blockIdx.z;
    const int hkv = h >> 2;

    {
        const int r0 = tid >> 4, d = (tid & 15) << 2;
        #pragma unroll
        for (int it = 0; it < 4; it++) {
            int r = r0 + it * 16;
            *(float4*)&Qs[r * ST + d] =
                *(const float4*)&g_Q[(size_t)(bb * S + qt * 64 + r) * (NH * DH) + h * DH + d];
        }
    }
    if (tid < 64) { m_s[tid] = -INFINITY; l_s[tid] = 0.f; }

    float o[4][4] = {};
    const float scale = 0.125f;

    for (int kt = 0; kt < S / 64; kt++) {
        __syncthreads();
        {
            const int r0 = tid >> 4, d = (tid & 15) << 2;
            #pragma unroll
            for (int it = 0; it < 4; it++) {
                int r = r0 + it * 16;
                size_t base = (size_t)(bb * S + kt * 64 + r) * (NKV * DH) + hkv * DH + d;
                *(float4*)&Ks[r * ST + d] = *(const float4*)&g_K[base];
                *(float4*)&Vs[r * ST + d] = *(const float4*)&g_V[base];
            }
        }
        __syncthreads();

        float sr[4][4] = {};
        #pragma unroll 4
        for (int d = 0; d < 64; d += 4) {
            float4 aq[4], kq[4];
            #pragma unroll
            for (int i = 0; i < 4; i++) aq[i] = *(const float4*)&Qs[(ty * 4 + i) * ST + d];
            #pragma unroll
            for (int j = 0; j < 4; j++) kq[j] = *(const float4*)&Ks[(tx * 4 + j) * ST + d];
            #pragma unroll
            for (int i = 0; i < 4; i++)
                #pragma unroll
                for (int j = 0; j < 4; j++) {
                    sr[i][j] = fmaf(aq[i].x, kq[j].x, sr[i][j]);
                    sr[i][j] = fmaf(aq[i].y, kq[j].y, sr[i][j]);
                    sr[i][j] = fmaf(aq[i].z, kq[j].z, sr[i][j]);
                    sr[i][j] = fmaf(aq[i].w, kq[j].w, sr[i][j]);
                }
        }

        {
            size_t boff = ((size_t)(bb * NH + h) * S + qt * 64) * S + kt * 64;
            size_t moff = ((size_t)bb * S + qt * 64) * S + kt * 64;
            #pragma unroll
            for (int i = 0; i < 4; i++) {
                int ql = ty * 4 + i;
                float4 b4 = *(const float4*)&bias[boff + (size_t)ql * S + tx * 4];
                int4   m4 = *(const int4*)  &mask[moff + (size_t)ql * S + tx * 4];
                float4 s;
                s.x = fmaf(sr[i][0], scale, b4.x); if (m4.x == 0) s.x = -1e9f;
                s.y = fmaf(sr[i][1], scale, b4.y); if (m4.y == 0) s.y = -1e9f;
                s.z = fmaf(sr[i][2], scale, b4.z); if (m4.z == 0) s.z = -1e9f;
                s.w = fmaf(sr[i][3], scale, b4.w); if (m4.w == 0) s.w = -1e9f;
                *(float4*)&Ss[ql * ST + tx * 4] = s;
            }
        }
        __syncthreads();

        {
            int row = tid >> 2, part = tid & 3;
            float* srow = Ss + row * ST + part * 16;
            float tmax = -INFINITY;
            #pragma unroll
            for (int c = 0; c < 16; c++) tmax = fmaxf(tmax, srow[c]);
            tmax = fmaxf(tmax, __shfl_xor_sync(0xffffffffu, tmax, 1));
            tmax = fmaxf(tmax, __shfl_xor_sync(0xffffffffu, tmax, 2));
            float mo = m_s[row];
            float mn = fmaxf(mo, tmax);
            float tsum = 0.f;
            #pragma unroll
            for (int c = 0; c < 16; c++) {
                float p = __expf(srow[c] - mn);
                srow[c] = p;
                tsum += p;
            }
            tsum += __shfl_xor_sync(0xffffffffu, tsum, 1);
            tsum += __shfl_xor_sync(0xffffffffu, tsum, 2);
            if (part == 0) {
                float alpha = __expf(mo - mn);
                al_s[row] = alpha;
                l_s[row]  = l_s[row] * alpha + tsum;
                m_s[row]  = mn;
            }
        }
        __syncthreads();

        {
            float al[4];
            #pragma unroll
            for (int i = 0; i < 4; i++) al[i] = al_s[ty * 4 + i];
            #pragma unroll
            for (int i = 0; i < 4; i++)
                #pragma unroll
                for (int j = 0; j < 4; j++) o[i][j] *= al[i];

            #pragma unroll 4
            for (int kk = 0; kk < 64; kk += 4) {
                float4 p4[4], v4[4];
                #pragma unroll
                for (int i = 0; i < 4; i++) p4[i] = *(const float4*)&Ss[(ty * 4 + i) * ST + kk];
                #pragma unroll
                for (int u = 0; u < 4; u++) v4[u] = *(const float4*)&Vs[(kk + u) * ST + tx * 4];
                #pragma unroll
                for (int i = 0; i < 4; i++) {
                    o[i][0] = fmaf(p4[i].x, v4[0].x, o[i][0]);
                    o[i][1] = fmaf(p4[i].x, v4[0].y, o[i][1]);
                    o[i][2] = fmaf(p4[i].x, v4[0].z, o[i][2]);
                    o[i][3] = fmaf(p4[i].x, v4[0].w, o[i][3]);
                    o[i][0] = fmaf(p4[i].y, v4[1].x, o[i][0]);
                    o[i][1] = fmaf(p4[i].y, v4[1].y, o[i][1]);
                    o[i][2] = fmaf(p4[i].y, v4[1].z, o[i][2]);
                    o[i][3] = fmaf(p4[i].y, v4[1].w, o[i][3]);
                    o[i][0] = fmaf(p4[i].z, v4[2].x, o[i][0]);
                    o[i][1] = fmaf(p4[i].z, v4[2].y, o[i][1]);
                    o[i][2] = fmaf(p4[i].z, v4[2].z, o[i][2]);
                    o[i][3] = fmaf(p4[i].z, v4[2].w, o[i][3]);
                    o[i][0] = fmaf(p4[i].w, v4[3].x, o[i][0]);
                    o[i][1] = fmaf(p4[i].w, v4[3].y, o[i][1]);
                    o[i][2] = fmaf(p4[i].w, v4[3].z, o[i][2]);
                    o[i][3] = fmaf(p4[i].w, v4[3].w, o[i][3]);
                }
            }
        }
    }
    __syncthreads();

    #pragma unroll
    for (int i = 0; i < 4; i++) {
        int ql = ty * 4 + i;
        float inv = 1.0f / l_s[ql];
        size_t base = (size_t)(bb * S + qt * 64 + ql) * (NH * DH) + h * DH + tx * 4;
        float4 r;
        r.x = o[i][0] * inv; r.y = o[i][1] * inv;
        r.z = o[i][2] * inv; r.w = o[i][3] * inv;
        *(float4*)&g_A[base] = r;
    }
}

// ---------------------------------------------------------------------------
extern "C" void kernel_launch(void* const* d_in, const int* in_sizes, int n_in,
                              void* d_out, int out_size)
{
    const float* X    = (const float*)d_in[0];
    const float* bias = (const float*)d_in[1];
    const int*   mask = (const int*  )d_in[2];
    const float* Wq   = (const float*)d_in[3];
    const float* Wk   = (const float*)d_in[4];
    const float* Wv   = (const float*)d_in[5];
    const float* Wo   = (const float*)d_in[6];
    float* out = (float*)d_out;

    float *pQ, *pK, *pV, *pA;
    cudaGetSymbolAddress((void**)&pQ, g_Q);
    cudaGetSymbolAddress((void**)&pK, g_K);
    cudaGetSymbolAddress((void**)&pV, g_V);
    cudaGetSymbolAddress((void**)&pA, g_A);
    __nv_bfloat16 *pXh, *pXl, *pAh, *pAl, *pQh, *pQl, *pKh, *pKl, *pVh, *pVl, *pOh, *pOl;
    cudaGetSymbolAddress((void**)&pXh, g_Xhi);  cudaGetSymbolAddress((void**)&pXl, g_Xlo);
    cudaGetSymbolAddress((void**)&pAh, g_Ahi);  cudaGetSymbolAddress((void**)&pAl, g_Alo);
    cudaGetSymbolAddress((void**)&pQh, g_WqThi); cudaGetSymbolAddress((void**)&pQl, g_WqTlo);
    cudaGetSymbolAddress((void**)&pKh, g_WkThi); cudaGetSymbolAddress((void**)&pKl, g_WkTlo);
    cudaGetSymbolAddress((void**)&pVh, g_WvThi); cudaGetSymbolAddress((void**)&pVl, g_WvTlo);
    cudaGetSymbolAddress((void**)&pOh, g_WoThi); cudaGetSymbolAddress((void**)&pOl, g_WoTlo);

    int asm_sz = (4 * 64 * ST + 3 * 64) * (int)sizeof(float);
    cudaFuncSetAttribute(attn_kernel, cudaFuncAttributeMaxDynamicSharedMemorySize, asm_sz);

    // splits + weight transposes
    split_kernel<<<(B*S*HID/4 + 255)/256, 256>>>(X, pXh, pXl, B*S*HID/4);
    transpose_split<<<dim3((NH*DH)/32,  HID/32), dim3(32, 8)>>>(Wq, pQh, pQl, HID, NH*DH);
    transpose_split<<<dim3((NKV*DH)/32, HID/32), dim3(32, 8)>>>(Wk, pKh, pKl, HID, NKV*DH);
    transpose_split<<<dim3((NKV*DH)/32, HID/32), dim3(32, 8)>>>(Wv, pVh, pVl, HID, NKV*DH);
    transpose_split<<<dim3(HID/32,      HID/32), dim3(32, 8)>>>(Wo, pOh, pOl, HID, HID);

    // projections (HMMA tensor cores)
    gemm_mma<<<dim3((NH*DH)/128,  (B*S)/128), 256>>>(pXh, pXl, pQh, pQl, pQ, B*S, NH*DH,  HID);
    gemm_mma<<<dim3((NKV*DH)/128, (B*S)/128), 256>>>(pXh, pXl, pKh, pKl, pK, B*S, NKV*DH, HID);
    gemm_mma<<<dim3((NKV*DH)/128, (B*S)/128), 256>>>(pXh, pXl, pVh, pVl, pV, B*S, NKV*DH, HID);

    // attention
    attn_kernel<<<dim3(S/64, NH, B), 256, asm_sz>>>(bias, mask);

    // output projection
    split_kernel<<<(B*S*HID/4 + 255)/256, 256>>>(pA, pAh, pAl, B*S*HID/4);
    gemm_mma<<<dim3(HID/128, (B*S)/128), 256>>>(pAh, pAl, pOh, pOl, out, B*S, HID, HID);
}

// round 4
// speedup vs baseline: 1.7843x; 1.7406x over previous
#include <cuda_runtime.h>
#include <cuda_bf16.h>
#include <math.h>
#include <stdint.h>

#define B   4
#define S   1024
#define HID 1024
#define NH  16
#define NKV 4
#define DH  64

// ---------------------------------------------------------------------------
// Scratch (allocation-free rule: __device__ globals)
// ---------------------------------------------------------------------------
__device__ __nv_bfloat16 g_Xhi[B*S*HID], g_Xlo[B*S*HID];
__device__ __nv_bfloat16 g_Qh[B*S*NH*DH],  g_Ql[B*S*NH*DH];
__device__ __nv_bfloat16 g_Kh[B*S*NKV*DH], g_Kl[B*S*NKV*DH];
__device__ __nv_bfloat16 g_Vh[B*S*NKV*DH], g_Vl[B*S*NKV*DH];
__device__ __nv_bfloat16 g_VTh[B*NKV*DH*S], g_VTl[B*NKV*DH*S];   // [b][hkv][d][s]
__device__ __nv_bfloat16 g_Ah[B*S*HID], g_Al[B*S*HID];
__device__ __nv_bfloat16 g_WqThi[HID*NH*DH],  g_WqTlo[HID*NH*DH];
__device__ __nv_bfloat16 g_WkThi[HID*NKV*DH], g_WkTlo[HID*NKV*DH];
__device__ __nv_bfloat16 g_WvThi[HID*NKV*DH], g_WvTlo[HID*NKV*DH];
__device__ __nv_bfloat16 g_WoThi[HID*HID],    g_WoTlo[HID*HID];

// ---------------------------------------------------------------------------
// mma.sync helpers (baseline PTX ok on sm_103)
// ---------------------------------------------------------------------------
__device__ __forceinline__ uint32_t smem_u32(const void* p) {
    uint32_t a;
    asm("{ .reg .u64 t; cvta.to.shared.u64 t, %1; cvt.u32.u64 %0, t; }" : "=r"(a) : "l"(p));
    return a;
}
__device__ __forceinline__ void ldmx4(uint32_t* r, uint32_t addr) {
    asm volatile("ldmatrix.sync.aligned.m8n8.x4.shared.b16 {%0,%1,%2,%3}, [%4];"
                 : "=r"(r[0]), "=r"(r[1]), "=r"(r[2]), "=r"(r[3]) : "r"(addr));
}
__device__ __forceinline__ void mma16816(float* d, const uint32_t* a, const uint32_t* b) {
    asm volatile("mma.sync.aligned.m16n8k16.row.col.f32.bf16.bf16.f32 "
                 "{%0,%1,%2,%3}, {%4,%5,%6,%7}, {%8,%9}, {%0,%1,%2,%3};"
                 : "+f"(d[0]), "+f"(d[1]), "+f"(d[2]), "+f"(d[3])
                 : "r"(a[0]), "r"(a[1]), "r"(a[2]), "r"(a[3]), "r"(b[0]), "r"(b[1]));
}
__device__ __forceinline__ uint32_t pack_hi(float a, float b, float& la, float& lb) {
    __nv_bfloat16 ha = __float2bfloat16(a), hb = __float2bfloat16(b);
    la = a - __bfloat162float(ha);
    lb = b - __bfloat162float(hb);
    __nv_bfloat162 p(ha, hb);
    return *(uint32_t*)&p;
}
__device__ __forceinline__ uint32_t pack_bf(float a, float b) {
    __nv_bfloat162 p(__float2bfloat16(a), __float2bfloat16(b));
    return *(uint32_t*)&p;
}

// ---------------------------------------------------------------------------
// fp32 -> bf16 hi/lo split
// ---------------------------------------------------------------------------
__global__ void split_kernel(const float* __restrict__ x,
                             __nv_bfloat16* __restrict__ hi,
                             __nv_bfloat16* __restrict__ lo, int n4)
{
    int i = blockIdx.x * 256 + threadIdx.x;
    if (i >= n4) return;
    float4 v = ((const float4*)x)[i];
    float l0, l1, l2, l3;
    uint32_t h01 = pack_hi(v.x, v.y, l0, l1);
    uint32_t h23 = pack_hi(v.z, v.w, l2, l3);
    ((uint32_t*)hi)[2*i]   = h01;
    ((uint32_t*)hi)[2*i+1] = h23;
    ((uint32_t*)lo)[2*i]   = pack_bf(l0, l1);
    ((uint32_t*)lo)[2*i+1] = pack_bf(l2, l3);
}

// W [K,N] fp32 -> W^T [N,K] bf16 hi/lo
__global__ void transpose_split(const float* __restrict__ W,
                                __nv_bfloat16* __restrict__ hiT,
                                __nv_bfloat16* __restrict__ loT, int K, int N)
{
    __shared__ float t[32][33];
    int n0 = blockIdx.x * 32, k0 = blockIdx.y * 32;
    int tx = threadIdx.x, ty = threadIdx.y;
    #pragma unroll
    for (int i = 0; i < 32; i += 8)
        t[ty + i][tx] = W[(size_t)(k0 + ty + i) * N + n0 + tx];
    __syncthreads();
    #pragma unroll
    for (int i = 0; i < 32; i += 8) {
        float v = t[tx][ty + i];
        __nv_bfloat16 h = __float2bfloat16(v);
        size_t o = (size_t)(n0 + ty + i) * K + k0 + tx;
        hiT[o] = h;
        loT[o] = __float2bfloat16(v - __bfloat162float(h));
    }
}

// V [b*s][256] bf16 hi/lo -> VT [b][hkv][64][1024] bf16 hi/lo
__global__ void vt_transpose(const __nv_bfloat16* __restrict__ Vh,
                             const __nv_bfloat16* __restrict__ Vl,
                             __nv_bfloat16* __restrict__ VTh,
                             __nv_bfloat16* __restrict__ VTl)
{
    __shared__ __nv_bfloat16 th[32][34], tl[32][34];
    int s0 = blockIdx.x * 32, d0 = blockIdx.y * 32, bh = blockIdx.z;
    int bb = bh >> 2, hkv = bh & 3;
    int tx = threadIdx.x, ty = threadIdx.y;
    #pragma unroll
    for (int i = 0; i < 32; i += 8) {
        size_t src = (size_t)(bb * S + s0 + ty + i) * (NKV * DH) + hkv * DH + d0 + tx;
        th[ty + i][tx] = Vh[src];
        tl[ty + i][tx] = Vl[src];
    }
    __syncthreads();
    #pragma unroll
    for (int i = 0; i < 32; i += 8) {
        size_t dst = (size_t)(bh * DH + d0 + ty + i) * S + s0 + tx;
        VTh[dst] = th[tx][ty + i];
        VTl[dst] = tl[tx][ty + i];
    }
}

// ---------------------------------------------------------------------------
// mma.sync split-bf16 GEMM: C = A[M,K] @ B^T (B as [N,K]).
// Output: fp32 C if Chi==null, else bf16 hi/lo split.
// ---------------------------------------------------------------------------
#define KC   32
#define ASTR 40

__global__ void __launch_bounds__(256)
gemm_mma(const __nv_bfloat16* __restrict__ Ahi, const __nv_bfloat16* __restrict__ Alo,
         const __nv_bfloat16* __restrict__ Bhi, const __nv_bfloat16* __restrict__ Blo,
         float* __restrict__ C, __nv_bfloat16* __restrict__ Chi, __nv_bfloat16* __restrict__ Clo,
         int M, int N, int K)
{
    __shared__ __nv_bfloat16 sA[2][128][ASTR];
    __shared__ __nv_bfloat16 sB[2][128][ASTR];

    const int tid = threadIdx.x, wid = tid >> 5, lane = tid & 31;
    const int wm = (wid & 3) * 32;
    const int wn = (wid >> 2) * 64;
    const int m0 = blockIdx.y * 128, n0 = blockIdx.x * 128;

    const int ldr = tid >> 1;
    const int ldc = (tid & 1) * 16;

    const int a_row = (lane & 15), a_col = (lane >> 4) * 8;
    const int b_row = (lane & 7) + ((lane >> 4) << 3), b_col = ((lane >> 3) & 1) * 8;

    const uint32_t sAh = smem_u32(&sA[0][0][0]), sAl = smem_u32(&sA[1][0][0]);
    const uint32_t sBh = smem_u32(&sB[0][0][0]), sBl = smem_u32(&sB[1][0][0]);

    float acc[2][8][4] = {};

    for (int k0 = 0; k0 < K; k0 += KC) {
        {
            size_t ga = (size_t)(m0 + ldr) * K + k0 + ldc;
            size_t gb = (size_t)(n0 + ldr) * K + k0 + ldc;
            *(uint4*)&sA[0][ldr][ldc]     = *(const uint4*)(Ahi + ga);
            *(uint4*)&sA[0][ldr][ldc + 8] = *(const uint4*)(Ahi + ga + 8);
            *(uint4*)&sA[1][ldr][ldc]     = *(const uint4*)(Alo + ga);
            *(uint4*)&sA[1][ldr][ldc + 8] = *(const uint4*)(Alo + ga + 8);
            *(uint4*)&sB[0][ldr][ldc]     = *(const uint4*)(Bhi + gb);
            *(uint4*)&sB[0][ldr][ldc + 8] = *(const uint4*)(Bhi + gb + 8);
            *(uint4*)&sB[1][ldr][ldc]     = *(const uint4*)(Blo + gb);
            *(uint4*)&sB[1][ldr][ldc + 8] = *(const uint4*)(Blo + gb + 8);
        }
        __syncthreads();

        #pragma unroll
        for (int kk = 0; kk < KC; kk += 16) {
            uint32_t ahi[2][4], alo[2][4], bhi[4][4], blo[4][4];
            #pragma unroll
            for (int mi = 0; mi < 2; mi++) {
                uint32_t off = ((wm + mi * 16 + a_row) * ASTR + kk + a_col) * 2;
                ldmx4(ahi[mi], sAh + off);
                ldmx4(alo[mi], sAl + off);
            }
            #pragma unroll
            for (int t = 0; t < 4; t++) {
                uint32_t off = ((wn + t * 16 + b_row) * ASTR + kk + b_col) * 2;
                ldmx4(bhi[t], sBh + off);
                ldmx4(blo[t], sBl + off);
            }
            #pragma unroll
            for (int mi = 0; mi < 2; mi++)
                #pragma unroll
                for (int nj = 0; nj < 8; nj++) {
                    const uint32_t* bh = &bhi[nj >> 1][(nj & 1) * 2];
                    const uint32_t* bl = &blo[nj >> 1][(nj & 1) * 2];
                    mma16816(acc[mi][nj], ahi[mi], bh);
                    mma16816(acc[mi][nj], ahi[mi], bl);
                    mma16816(acc[mi][nj], alo[mi], bh);
                }
        }
        __syncthreads();
    }

    #pragma unroll
    for (int mi = 0; mi < 2; mi++) {
        int row = m0 + wm + mi * 16 + (lane >> 2);
        #pragma unroll
        for (int nj = 0; nj < 8; nj++) {
            int col = n0 + wn + nj * 8 + (lane & 3) * 2;
            if (Chi) {
                float l0, l1, l2, l3;
                uint32_t h01 = pack_hi(acc[mi][nj][0], acc[mi][nj][1], l0, l1);
                uint32_t h23 = pack_hi(acc[mi][nj][2], acc[mi][nj][3], l2, l3);
                *(uint32_t*)&Chi[(size_t)row * N + col]       = h01;
                *(uint32_t*)&Clo[(size_t)row * N + col]       = pack_bf(l0, l1);
                *(uint32_t*)&Chi[(size_t)(row + 8) * N + col] = h23;
                *(uint32_t*)&Clo[(size_t)(row + 8) * N + col] = pack_bf(l2, l3);
            } else {
                *(float2*)&C[(size_t)row * N + col]       = make_float2(acc[mi][nj][0], acc[mi][nj][1]);
                *(float2*)&C[(size_t)(row + 8) * N + col] = make_float2(acc[mi][nj][2], acc[mi][nj][3]);
            }
        }
    }
}

// ---------------------------------------------------------------------------
// Flash attention on mma.sync. CTA = (64-q tile, h, b); 128 threads = 4 warps,
// each warp owns 16 q rows. K-tiles of 64. All matmuls split-bf16 (3 MMAs).
// ---------------------------------------------------------------------------
#define TSTR 72                   // smem row stride (bf16), 144B
#define TILE_E (64 * TSTR)        // elems per tile buffer

__global__ void __launch_bounds__(128)
attn_mma(const float* __restrict__ bias, const int* __restrict__ mask,
         __nv_bfloat16* __restrict__ Ah, __nv_bfloat16* __restrict__ Al)
{
    extern __shared__ __nv_bfloat16 smb[];
    __nv_bfloat16* sQh = smb;
    __nv_bfloat16* sQl = sQh + TILE_E;
    __nv_bfloat16* sKh = sQl + TILE_E;
    __nv_bfloat16* sKl = sKh + TILE_E;
    __nv_bfloat16* sVh = sKl + TILE_E;
    __nv_bfloat16* sVl = sVh + TILE_E;
    const uint32_t aQh = smem_u32(sQh), aQl = smem_u32(sQl);
    const uint32_t aKh = smem_u32(sKh), aKl = smem_u32(sKl);
    const uint32_t aVh = smem_u32(sVh), aVl = smem_u32(sVl);

    const int tid = threadIdx.x, wid = tid >> 5, lane = tid & 31;
    const int qt = blockIdx.x, h = blockIdx.y, bb = blockIdx.z;
    const int hkv = h >> 2;
    const int wm = wid * 16;

    const int a_row = (lane & 15), a_col = (lane >> 4) * 8;
    const int b_row = (lane & 7) + ((lane >> 4) << 3), b_col = ((lane >> 3) & 1) * 8;
    const int r = lane >> 2, qc = (lane & 3) * 2;

    // load Q tile [64 rows x 64 d], hi+lo
    #pragma unroll
    for (int i = 0; i < 4; i++) {
        int idx = tid + i * 128;
        int rr = idx >> 3, c = (idx & 7) * 8;
        size_t g = (size_t)(bb * S + qt * 64 + rr) * (NH * DH) + h * DH + c;
        *(uint4*)&sQh[rr * TSTR + c] = *(const uint4*)&g_Qh[g];
        *(uint4*)&sQl[rr * TSTR + c] = *(const uint4*)&g_Ql[g];
    }

    float oacc[8][4] = {};
    float m0 = -INFINITY, m1 = -INFINITY, l0 = 0.f, l1 = 0.f;

    for (int kt = 0; kt < S / 64; kt++) {
        __syncthreads();
        #pragma unroll
        for (int i = 0; i < 4; i++) {
            int idx = tid + i * 128;
            int rr = idx >> 3, c = (idx & 7) * 8;
            size_t gk = (size_t)(bb * S + kt * 64 + rr) * (NKV * DH) + hkv * DH + c;
            *(uint4*)&sKh[rr * TSTR + c] = *(const uint4*)&g_Kh[gk];
            *(uint4*)&sKl[rr * TSTR + c] = *(const uint4*)&g_Kl[gk];
            size_t gv = (size_t)((bb * NKV + hkv) * DH + rr) * S + kt * 64 + c;
            *(uint4*)&sVh[rr * TSTR + c] = *(const uint4*)&g_VTh[gv];
            *(uint4*)&sVl[rr * TSTR + c] = *(const uint4*)&g_VTl[gv];
        }
        __syncthreads();

        // S = Q K^T (split, 3 products)
        float sacc[8][4] = {};
        #pragma unroll
        for (int kk = 0; kk < 64; kk += 16) {
            uint32_t qh[4], ql[4], kh[4][4], kl[4][4];
            uint32_t offA = ((wm + a_row) * TSTR + kk + a_col) * 2;
            ldmx4(qh, aQh + offA);
            ldmx4(ql, aQl + offA);
            #pragma unroll
            for (int t = 0; t < 4; t++) {
                uint32_t offB = ((t * 16 + b_row) * TSTR + kk + b_col) * 2;
                ldmx4(kh[t], aKh + offB);
                ldmx4(kl[t], aKl + offB);
            }
            #pragma unroll
            for (int nj = 0; nj < 8; nj++) {
                const uint32_t* bh = &kh[nj >> 1][(nj & 1) * 2];
                const uint32_t* bl = &kl[nj >> 1][(nj & 1) * 2];
                mma16816(sacc[nj], qh, bh);
                mma16816(sacc[nj], qh, bl);
                mma16816(sacc[nj], ql, bh);
            }
        }

        // scale + bias + mask
        {
            int row0 = qt * 64 + wm + r;
            const float* bp = bias + ((size_t)(bb * NH + h) * S + row0) * S + kt * 64 + qc;
            const int*   mp = mask + ((size_t)bb * S + row0) * S + kt * 64 + qc;
            #pragma unroll
            for (int nj = 0; nj < 8; nj++) {
                float2 bv = *(const float2*)(bp + nj * 8);
                int2   mv = *(const int2*)  (mp + nj * 8);
                sacc[nj][0] = mv.x ? fmaf(sacc[nj][0], 0.125f, bv.x) : -1e9f;
                sacc[nj][1] = mv.y ? fmaf(sacc[nj][1], 0.125f, bv.y) : -1e9f;
                float2 bv2 = *(const float2*)(bp + 8 * S + nj * 8);
                int2   mv2 = *(const int2*)  (mp + 8 * S + nj * 8);
                sacc[nj][2] = mv2.x ? fmaf(sacc[nj][2], 0.125f, bv2.x) : -1e9f;
                sacc[nj][3] = mv2.y ? fmaf(sacc[nj][3], 0.125f, bv2.y) : -1e9f;
            }
        }

        // online softmax (rows r and r+8 per lane; reduce over 4-lane group)
        float mx0 = -INFINITY, mx1 = -INFINITY;
        #pragma unroll
        for (int nj = 0; nj < 8; nj++) {
            mx0 = fmaxf(mx0, fmaxf(sacc[nj][0], sacc[nj][1]));
            mx1 = fmaxf(mx1, fmaxf(sacc[nj][2], sacc[nj][3]));
        }
        mx0 = fmaxf(mx0, __shfl_xor_sync(0xffffffffu, mx0, 1));
        mx0 = fmaxf(mx0, __shfl_xor_sync(0xffffffffu, mx0, 2));
        mx1 = fmaxf(mx1, __shfl_xor_sync(0xffffffffu, mx1, 1));
        mx1 = fmaxf(mx1, __shfl_xor_sync(0xffffffffu, mx1, 2));
        float mn0 = fmaxf(m0, mx0), mn1 = fmaxf(m1, mx1);
        float alpha0 = __expf(m0 - mn0), alpha1 = __expf(m1 - mn1);
        m0 = mn0; m1 = mn1;

        float ts0 = 0.f, ts1 = 0.f;
        uint32_t ph[8][2], pl[8][2];
        #pragma unroll
        for (int nj = 0; nj < 8; nj++) {
            float p0 = __expf(sacc[nj][0] - mn0);
            float p1 = __expf(sacc[nj][1] - mn0);
            float p2 = __expf(sacc[nj][2] - mn1);
            float p3 = __expf(sacc[nj][3] - mn1);
            ts0 += p0 + p1;
            ts1 += p2 + p3;
            float q0, q1, q2, q3;
            ph[nj][0] = pack_hi(p0, p1, q0, q1);
            ph[nj][1] = pack_hi(p2, p3, q2, q3);
            pl[nj][0] = pack_bf(q0, q1);
            pl[nj][1] = pack_bf(q2, q3);
        }
        ts0 += __shfl_xor_sync(0xffffffffu, ts0, 1);
        ts0 += __shfl_xor_sync(0xffffffffu, ts0, 2);
        ts1 += __shfl_xor_sync(0xffffffffu, ts1, 1);
        ts1 += __shfl_xor_sync(0xffffffffu, ts1, 2);
        l0 = l0 * alpha0 + ts0;
        l1 = l1 * alpha1 + ts1;

        #pragma unroll
        for (int nj = 0; nj < 8; nj++) {
            oacc[nj][0] *= alpha0; oacc[nj][1] *= alpha0;
            oacc[nj][2] *= alpha1; oacc[nj][3] *= alpha1;
        }

        // O += P @ V   (A = P fragments from registers, B = VT tiles)
        #pragma unroll
        for (int kk = 0; kk < 64; kk += 16) {
            int nt = kk >> 3;
            uint32_t aPh[4] = { ph[nt][0], ph[nt][1], ph[nt + 1][0], ph[nt + 1][1] };
            uint32_t aPl[4] = { pl[nt][0], pl[nt][1], pl[nt + 1][0], pl[nt + 1][1] };
            uint32_t vh[4][4], vl[4][4];
            #pragma unroll
            for (int t = 0; t < 4; t++) {
                uint32_t offV = ((t * 16 + b_row) * TSTR + kk + b_col) * 2;
                ldmx4(vh[t], aVh + offV);
                ldmx4(vl[t], aVl + offV);
            }
            #pragma unroll
            for (int nj = 0; nj < 8; nj++) {
                const uint32_t* bh = &vh[nj >> 1][(nj & 1) * 2];
                const uint32_t* bl = &vl[nj >> 1][(nj & 1) * 2];
                mma16816(oacc[nj], aPh, bh);
                mma16816(oacc[nj], aPh, bl);
                mma16816(oacc[nj], aPl, bh);
            }
        }
    }

    // epilogue: normalize, split to bf16 hi/lo, store
    float inv0 = 1.0f / l0, inv1 = 1.0f / l1;
    int rowA = bb * S + qt * 64 + wm + r;
    #pragma unroll
    for (int nj = 0; nj < 8; nj++) {
        int col = h * DH + nj * 8 + qc;
        float q0, q1, q2, q3;
        uint32_t h01 = pack_hi(oacc[nj][0] * inv0, oacc[nj][1] * inv0, q0, q1);
        uint32_t h23 = pack_hi(oacc[nj][2] * inv1, oacc[nj][3] * inv1, q2, q3);
        *(uint32_t*)&Ah[(size_t)rowA * HID + col]       = h01;
        *(uint32_t*)&Al[(size_t)rowA * HID + col]       = pack_bf(q0, q1);
        *(uint32_t*)&Ah[(size_t)(rowA + 8) * HID + col] = h23;
        *(uint32_t*)&Al[(size_t)(rowA + 8) * HID + col] = pack_bf(q2, q3);
    }
}

// ---------------------------------------------------------------------------
extern "C" void kernel_launch(void* const* d_in, const int* in_sizes, int n_in,
                              void* d_out, int out_size)
{
    const float* X    = (const float*)d_in[0];
    const float* bias = (const float*)d_in[1];
    const int*   mask = (const int*  )d_in[2];
    const float* Wq   = (const float*)d_in[3];
    const float* Wk   = (const float*)d_in[4];
    const float* Wv   = (const float*)d_in[5];
    const float* Wo   = (const float*)d_in[6];
    float* out = (float*)d_out;

    __nv_bfloat16 *pXh, *pXl, *pQh, *pQl, *pKh, *pKl, *pVh, *pVl, *pVTh, *pVTl, *pAh, *pAl;
    __nv_bfloat16 *pWq, *pWq2, *pWk, *pWk2, *pWv, *pWv2, *pWo, *pWo2;
    cudaGetSymbolAddress((void**)&pXh, g_Xhi);   cudaGetSymbolAddress((void**)&pXl, g_Xlo);
    cudaGetSymbolAddress((void**)&pQh, g_Qh);    cudaGetSymbolAddress((void**)&pQl, g_Ql);
    cudaGetSymbolAddress((void**)&pKh, g_Kh);    cudaGetSymbolAddress((void**)&pKl, g_Kl);
    cudaGetSymbolAddress((void**)&pVh, g_Vh);    cudaGetSymbolAddress((void**)&pVl, g_Vl);
    cudaGetSymbolAddress((void**)&pVTh, g_VTh);  cudaGetSymbolAddress((void**)&pVTl, g_VTl);
    cudaGetSymbolAddress((void**)&pAh, g_Ah);    cudaGetSymbolAddress((void**)&pAl, g_Al);
    cudaGetSymbolAddress((void**)&pWq, g_WqThi); cudaGetSymbolAddress((void**)&pWq2, g_WqTlo);
    cudaGetSymbolAddress((void**)&pWk, g_WkThi); cudaGetSymbolAddress((void**)&pWk2, g_WkTlo);
    cudaGetSymbolAddress((void**)&pWv, g_WvThi); cudaGetSymbolAddress((void**)&pWv2, g_WvTlo);
    cudaGetSymbolAddress((void**)&pWo, g_WoThi); cudaGetSymbolAddress((void**)&pWo2, g_WoTlo);

    int attn_smem = 6 * TILE_E * (int)sizeof(__nv_bfloat16);   // 55296
    cudaFuncSetAttribute(attn_mma, cudaFuncAttributeMaxDynamicSharedMemorySize, attn_smem);

    // prep
    split_kernel<<<(B*S*HID/4 + 255)/256, 256>>>(X, pXh, pXl, B*S*HID/4);
    transpose_split<<<dim3((NH*DH)/32,  HID/32), dim3(32, 8)>>>(Wq, pWq, pWq2, HID, NH*DH);
    transpose_split<<<dim3((NKV*DH)/32, HID/32), dim3(32, 8)>>>(Wk, pWk, pWk2, HID, NKV*DH);
    transpose_split<<<dim3((NKV*DH)/32, HID/32), dim3(32, 8)>>>(Wv, pWv, pWv2, HID, NKV*DH);
    transpose_split<<<dim3(HID/32,      HID/32), dim3(32, 8)>>>(Wo, pWo, pWo2, HID, HID);

    // projections -> bf16 hi/lo
    gemm_mma<<<dim3((NH*DH)/128,  (B*S)/128), 256>>>(pXh, pXl, pWq, pWq2, nullptr, pQh, pQl, B*S, NH*DH,  HID);
    gemm_mma<<<dim3((NKV*DH)/128, (B*S)/128), 256>>>(pXh, pXl, pWk, pWk2, nullptr, pKh, pKl, B*S, NKV*DH, HID);
    gemm_mma<<<dim3((NKV*DH)/128, (B*S)/128), 256>>>(pXh, pXl, pWv, pWv2, nullptr, pVh, pVl, B*S, NKV*DH, HID);
    vt_transpose<<<dim3(S/32, DH/32, B*NKV), dim3(32, 8)>>>(pVh, pVl, pVTh, pVTl);

    // attention (tensor cores)
    attn_mma<<<dim3(S/64, NH, B), 128, attn_smem>>>(bias, mask, pAh, pAl);

    // output projection -> fp32 out
    gemm_mma<<<dim3(HID/128, (B*S)/128), 256>>>(pAh, pAl, pWo, pWo2, out, nullptr, nullptr, B*S, HID, HID);
}

// round 5
// speedup vs baseline: 2.1385x; 1.1985x over previous
#include <cuda_runtime.h>
#include <cuda_bf16.h>
#include <math.h>
#include <stdint.h>

#define B   4
#define S   1024
#define HID 1024
#define NH  16
#define NKV 4
#define DH  64

// ---------------------------------------------------------------------------
// Scratch (allocation-free rule: __device__ globals)
// ---------------------------------------------------------------------------
__device__ __nv_bfloat16 g_Xhi[B*S*HID], g_Xlo[B*S*HID];
__device__ __nv_bfloat16 g_Qh[B*S*NH*DH],  g_Ql[B*S*NH*DH];
__device__ __nv_bfloat16 g_Kh[B*S*NKV*DH], g_Kl[B*S*NKV*DH];
__device__ __nv_bfloat16 g_Vh[B*S*NKV*DH], g_Vl[B*S*NKV*DH];
__device__ __nv_bfloat16 g_VTh[B*NKV*DH*S], g_VTl[B*NKV*DH*S];   // [b][hkv][d][s]
__device__ __nv_bfloat16 g_Ah[B*S*HID], g_Al[B*S*HID];
__device__ __nv_bfloat16 g_WqThi[HID*NH*DH],  g_WqTlo[HID*NH*DH];
__device__ __nv_bfloat16 g_WkThi[HID*NKV*DH], g_WkTlo[HID*NKV*DH];
__device__ __nv_bfloat16 g_WvThi[HID*NKV*DH], g_WvTlo[HID*NKV*DH];
__device__ __nv_bfloat16 g_WoThi[HID*HID],    g_WoTlo[HID*HID];
__device__ uint2 g_Mbits[B*S*(S/64)];   // packed mask bits: [row][word64] -> {even cols, odd cols}

// ---------------------------------------------------------------------------
// helpers
// ---------------------------------------------------------------------------
__device__ __forceinline__ uint32_t smem_u32(const void* p) {
    uint32_t a;
    asm("{ .reg .u64 t; cvta.to.shared.u64 t, %1; cvt.u32.u64 %0, t; }" : "=r"(a) : "l"(p));
    return a;
}
__device__ __forceinline__ void ldmx4(uint32_t* r, uint32_t addr) {
    asm volatile("ldmatrix.sync.aligned.m8n8.x4.shared.b16 {%0,%1,%2,%3}, [%4];"
                 : "=r"(r[0]), "=r"(r[1]), "=r"(r[2]), "=r"(r[3]) : "r"(addr));
}
__device__ __forceinline__ void mma16816(float* d, const uint32_t* a, const uint32_t* b) {
    asm volatile("mma.sync.aligned.m16n8k16.row.col.f32.bf16.bf16.f32 "
                 "{%0,%1,%2,%3}, {%4,%5,%6,%7}, {%8,%9}, {%0,%1,%2,%3};"
                 : "+f"(d[0]), "+f"(d[1]), "+f"(d[2]), "+f"(d[3])
                 : "r"(a[0]), "r"(a[1]), "r"(a[2]), "r"(a[3]), "r"(b[0]), "r"(b[1]));
}
__device__ __forceinline__ uint32_t pack_hi(float a, float b, float& la, float& lb) {
    __nv_bfloat16 ha = __float2bfloat16(a), hb = __float2bfloat16(b);
    la = a - __bfloat162float(ha);
    lb = b - __bfloat162float(hb);
    __nv_bfloat162 p(ha, hb);
    return *(uint32_t*)&p;
}
__device__ __forceinline__ uint32_t pack_bf(float a, float b) {
    __nv_bfloat162 p(__float2bfloat16(a), __float2bfloat16(b));
    return *(uint32_t*)&p;
}
#define CPA16(dst, src) asm volatile("cp.async.cg.shared.global [%0], [%1], 16;" :: "r"(dst), "l"(src))
#define CP_COMMIT()     asm volatile("cp.async.commit_group;")
#define CP_WAIT(n)      asm volatile("cp.async.wait_group %0;" :: "n"(n))

// ---------------------------------------------------------------------------
// prep kernels
// ---------------------------------------------------------------------------
__global__ void split_kernel(const float* __restrict__ x,
                             __nv_bfloat16* __restrict__ hi,
                             __nv_bfloat16* __restrict__ lo, int n4)
{
    int i = blockIdx.x * 256 + threadIdx.x;
    if (i >= n4) return;
    float4 v = ((const float4*)x)[i];
    float l0, l1, l2, l3;
    uint32_t h01 = pack_hi(v.x, v.y, l0, l1);
    uint32_t h23 = pack_hi(v.z, v.w, l2, l3);
    ((uint32_t*)hi)[2*i]   = h01;
    ((uint32_t*)hi)[2*i+1] = h23;
    ((uint32_t*)lo)[2*i]   = pack_bf(l0, l1);
    ((uint32_t*)lo)[2*i+1] = pack_bf(l2, l3);
}

__global__ void transpose_split(const float* __restrict__ W,
                                __nv_bfloat16* __restrict__ hiT,
                                __nv_bfloat16* __restrict__ loT, int K, int N)
{
    __shared__ float t[32][33];
    int n0 = blockIdx.x * 32, k0 = blockIdx.y * 32;
    int tx = threadIdx.x, ty = threadIdx.y;
    #pragma unroll
    for (int i = 0; i < 32; i += 8)
        t[ty + i][tx] = W[(size_t)(k0 + ty + i) * N + n0 + tx];
    __syncthreads();
    #pragma unroll
    for (int i = 0; i < 32; i += 8) {
        float v = t[tx][ty + i];
        __nv_bfloat16 h = __float2bfloat16(v);
        size_t o = (size_t)(n0 + ty + i) * K + k0 + tx;
        hiT[o] = h;
        loT[o] = __float2bfloat16(v - __bfloat162float(h));
    }
}

__global__ void vt_transpose(const __nv_bfloat16* __restrict__ Vh,
                             const __nv_bfloat16* __restrict__ Vl,
                             __nv_bfloat16* __restrict__ VTh,
                             __nv_bfloat16* __restrict__ VTl)
{
    __shared__ __nv_bfloat16 th[32][34], tl[32][34];
    int s0 = blockIdx.x * 32, d0 = blockIdx.y * 32, bh = blockIdx.z;
    int bb = bh >> 2, hkv = bh & 3;
    int tx = threadIdx.x, ty = threadIdx.y;
    #pragma unroll
    for (int i = 0; i < 32; i += 8) {
        size_t src = (size_t)(bb * S + s0 + ty + i) * (NKV * DH) + hkv * DH + d0 + tx;
        th[ty + i][tx] = Vh[src];
        tl[ty + i][tx] = Vl[src];
    }
    __syncthreads();
    #pragma unroll
    for (int i = 0; i < 32; i += 8) {
        size_t dst = (size_t)(bh * DH + d0 + ty + i) * S + s0 + tx;
        VTh[dst] = th[tx][ty + i];
        VTl[dst] = tl[tx][ty + i];
    }
}

// pack mask -> bits. One block per row, warp w packs 64-col word w.
__global__ void maskpack(const int* __restrict__ mask)
{
    int row = blockIdx.x;                 // 0 .. B*S-1
    int w = threadIdx.x >> 5, lane = threadIdx.x & 31;
    int2 m = *(const int2*)(mask + (size_t)row * S + w * 64 + lane * 2);
    uint32_t b0 = __ballot_sync(0xffffffffu, m.x != 0);
    uint32_t b1 = __ballot_sync(0xffffffffu, m.y != 0);
    if (lane == 0) g_Mbits[row * (S/64) + w] = make_uint2(b0, b1);
}

// ---------------------------------------------------------------------------
// split-bf16 GEMM, 2-stage cp.async pipeline. C = A[M,K] @ B^T (B as [N,K]).
// ---------------------------------------------------------------------------
#define KC   32
#define ASTR 40
#define GT_E (128 * ASTR)                 // elems per tile buffer
#define GEMM_SMEM (2 * 4 * GT_E * 2)      // 2 stages x 4 tiles x bf16

__global__ void __launch_bounds__(256)
gemm_mma(const __nv_bfloat16* __restrict__ Ahi, const __nv_bfloat16* __restrict__ Alo,
         const __nv_bfloat16* __restrict__ Bhi, const __nv_bfloat16* __restrict__ Blo,
         float* __restrict__ C, __nv_bfloat16* __restrict__ Chi, __nv_bfloat16* __restrict__ Clo,
         int M, int N, int K)
{
    extern __shared__ __nv_bfloat16 smg[];
    const uint32_t sbase = smem_u32(smg);

    const int tid = threadIdx.x, wid = tid >> 5, lane = tid & 31;
    const int wm = (wid & 3) * 32;
    const int wn = (wid >> 2) * 64;
    const int m0 = blockIdx.y * 128, n0 = blockIdx.x * 128;

    const int ldr = tid >> 1;
    const int ldc = (tid & 1) * 16;

    const int a_row = (lane & 15), a_col = (lane >> 4) * 8;
    const int b_row = (lane & 7) + ((lane >> 4) << 3), b_col = ((lane >> 3) & 1) * 8;

    const __nv_bfloat16* srcs[4] = { Ahi, Alo, Bhi, Blo };
    const int rowbase[2] = { m0, n0 };

    float acc[2][8][4] = {};
    const int KI = K / KC;

    // prologue: stage 0
    #pragma unroll
    for (int t = 0; t < 4; t++) {
        size_t g = (size_t)(rowbase[t >> 1] + ldr) * K + ldc;
        uint32_t d = sbase + (uint32_t)(t * GT_E + ldr * ASTR + ldc) * 2;
        CPA16(d, srcs[t] + g);
        CPA16(d + 16, srcs[t] + g + 8);
    }
    CP_COMMIT();

    for (int kt = 0; kt < KI; kt++) {
        const int cur = kt & 1;
        if (kt + 1 < KI) {
            const int nxt = (kt + 1) & 1;
            int k0 = (kt + 1) * KC;
            #pragma unroll
            for (int t = 0; t < 4; t++) {
                size_t g = (size_t)(rowbase[t >> 1] + ldr) * K + k0 + ldc;
                uint32_t d = sbase + (uint32_t)((nxt * 4 + t) * GT_E + ldr * ASTR + ldc) * 2;
                CPA16(d, srcs[t] + g);
                CPA16(d + 16, srcs[t] + g + 8);
            }
            CP_COMMIT();
            CP_WAIT(1);
        } else {
            CP_WAIT(0);
        }
        __syncthreads();

        const uint32_t sAh = sbase + (uint32_t)((cur * 4 + 0) * GT_E) * 2;
        const uint32_t sAl = sbase + (uint32_t)((cur * 4 + 1) * GT_E) * 2;
        const uint32_t sBh = sbase + (uint32_t)((cur * 4 + 2) * GT_E) * 2;
        const uint32_t sBl = sbase + (uint32_t)((cur * 4 + 3) * GT_E) * 2;

        #pragma unroll
        for (int kk = 0; kk < KC; kk += 16) {
            uint32_t ahi[2][4], alo[2][4], bhi[4][4], blo[4][4];
            #pragma unroll
            for (int mi = 0; mi < 2; mi++) {
                uint32_t off = ((wm + mi * 16 + a_row) * ASTR + kk + a_col) * 2;
                ldmx4(ahi[mi], sAh + off);
                ldmx4(alo[mi], sAl + off);
            }
            #pragma unroll
            for (int t = 0; t < 4; t++) {
                uint32_t off = ((wn + t * 16 + b_row) * ASTR + kk + b_col) * 2;
                ldmx4(bhi[t], sBh + off);
                ldmx4(blo[t], sBl + off);
            }
            #pragma unroll
            for (int mi = 0; mi < 2; mi++)
                #pragma unroll
                for (int nj = 0; nj < 8; nj++) {
                    const uint32_t* bh = &bhi[nj >> 1][(nj & 1) * 2];
                    const uint32_t* bl = &blo[nj >> 1][(nj & 1) * 2];
                    mma16816(acc[mi][nj], ahi[mi], bh);
                    mma16816(acc[mi][nj], ahi[mi], bl);
                    mma16816(acc[mi][nj], alo[mi], bh);
                }
        }
        __syncthreads();
    }

    #pragma unroll
    for (int mi = 0; mi < 2; mi++) {
        int row = m0 + wm + mi * 16 + (lane >> 2);
        #pragma unroll
        for (int nj = 0; nj < 8; nj++) {
            int col = n0 + wn + nj * 8 + (lane & 3) * 2;
            if (Chi) {
                float l0, l1, l2, l3;
                uint32_t h01 = pack_hi(acc[mi][nj][0], acc[mi][nj][1], l0, l1);
                uint32_t h23 = pack_hi(acc[mi][nj][2], acc[mi][nj][3], l2, l3);
                *(uint32_t*)&Chi[(size_t)row * N + col]       = h01;
                *(uint32_t*)&Clo[(size_t)row * N + col]       = pack_bf(l0, l1);
                *(uint32_t*)&Chi[(size_t)(row + 8) * N + col] = h23;
                *(uint32_t*)&Clo[(size_t)(row + 8) * N + col] = pack_bf(l2, l3);
            } else {
                *(float2*)&C[(size_t)row * N + col]       = make_float2(acc[mi][nj][0], acc[mi][nj][1]);
                *(float2*)&C[(size_t)(row + 8) * N + col] = make_float2(acc[mi][nj][2], acc[mi][nj][3]);
            }
        }
    }
}

// ---------------------------------------------------------------------------
// Flash attention, mma.sync, q-tile 128, 8 warps, 2-stage cp.async K/V,
// bias prefetched in registers, mask via packed bits.
// ---------------------------------------------------------------------------
#define TSTR 72
#define QT_E (128 * TSTR)                 // Q buffer elems (one of hi/lo)
#define KV_E (64 * TSTR)                  // one K/V tile buffer elems
#define ATTN_SMEM ((2 * QT_E + 2 * 4 * KV_E) * 2)

__global__ void __launch_bounds__(256)
attn_mma(const float* __restrict__ bias,
         __nv_bfloat16* __restrict__ Ah, __nv_bfloat16* __restrict__ Al)
{
    extern __shared__ __nv_bfloat16 smb[];
    const uint32_t aQh = smem_u32(smb);
    const uint32_t aQl = aQh + QT_E * 2;
    const uint32_t kvbase = aQl + QT_E * 2;   // [stage][Kh,Kl,Vh,Vl]

    const int tid = threadIdx.x, wid = tid >> 5, lane = tid & 31;
    const int qt = blockIdx.x, h = blockIdx.y, bb = blockIdx.z;
    const int hkv = h >> 2;
    const int wm = wid * 16;

    const int a_row = (lane & 15), a_col = (lane >> 4) * 8;
    const int b_row = (lane & 7) + ((lane >> 4) << 3), b_col = ((lane >> 3) & 1) * 8;
    const int r = lane >> 2, qc = (lane & 3) * 2;

    // Q tile [128 x 64] hi/lo via regular ld/st
    #pragma unroll
    for (int i = 0; i < 4; i++) {
        int idx = tid + i * 256;
        int rr = idx >> 3, c = (idx & 7) * 8;
        size_t g = (size_t)(bb * S + qt * 128 + rr) * (NH * DH) + h * DH + c;
        *(uint4*)(smb + rr * TSTR + c)          = *(const uint4*)&g_Qh[g];
        *(uint4*)(smb + QT_E + rr * TSTR + c)   = *(const uint4*)&g_Ql[g];
    }

    const __nv_bfloat16* kvsrc[4];
    kvsrc[0] = g_Kh + (size_t)bb * S * (NKV * DH) + hkv * DH;
    kvsrc[1] = g_Kl + (size_t)bb * S * (NKV * DH) + hkv * DH;
    kvsrc[2] = g_VTh + (size_t)((bb * NKV + hkv) * DH) * S;
    kvsrc[3] = g_VTl + (size_t)((bb * NKV + hkv) * DH) * S;

    // cp.async loader: 8 chunks per stage per thread
    const int ltile = tid >> 6;               // 0..3 -> Kh,Kl,Vh,Vl
    const int lidx = tid & 63;                // 64 threads per tile, 8 chunks each

    // prologue: stage 0 (kt = 0)
    #pragma unroll
    for (int j = 0; j < 8; j++) {
        int ch = lidx + j * 64;               // 0..511
        int rr = ch >> 3, c = (ch & 7) * 8;
        uint32_t d = kvbase + (uint32_t)(ltile * KV_E + rr * TSTR + c) * 2;
        size_t g = (ltile < 2) ? (size_t)rr * (NKV * DH) + c          // K rows over seq
                               : (size_t)rr * S + c;                   // VT rows over d
        CPA16(d, kvsrc[ltile] + g);
    }
    CP_COMMIT();

    float oacc[8][4] = {};
    float m0 = -INFINITY, m1 = -INFINITY, l0 = 0.f, l1 = 0.f;
    const int row0 = qt * 128 + wm + r;
    const float* bprow = bias + ((size_t)(bb * NH + h) * S + row0) * S + qc;
    const uint2* mrow0 = g_Mbits + (size_t)(bb * S + row0) * (S/64);
    const uint2* mrow1 = mrow0 + 8 * (S/64);

    for (int kt = 0; kt < S / 64; kt++) {
        const int cur = kt & 1;
        if (kt + 1 < S / 64) {
            const int nxt = (kt + 1) & 1;
            int s0 = (kt + 1) * 64;
            #pragma unroll
            for (int j = 0; j < 8; j++) {
                int ch = lidx + j * 64;
                int rr = ch >> 3, c = (ch & 7) * 8;
                uint32_t d = kvbase + (uint32_t)((nxt * 4 + ltile) * KV_E + rr * TSTR + c) * 2;
                size_t g = (ltile < 2) ? (size_t)(s0 + rr) * (NKV * DH) + c
                                       : (size_t)rr * S + s0 + c;
                CPA16(d, kvsrc[ltile] + g);
            }
            CP_COMMIT();
        }

        // prefetch bias + mask bits for this tile (overlaps wait + MMA)
        float2 bvA[8], bvB[8];
        const float* bp = bprow + (size_t)kt * 64;
        #pragma unroll
        for (int nj = 0; nj < 8; nj++) {
            bvA[nj] = *(const float2*)(bp + nj * 8);
            bvB[nj] = *(const float2*)(bp + 8 * S + nj * 8);
        }
        uint2 mwA = mrow0[kt], mwB = mrow1[kt];

        if (kt + 1 < S / 64) CP_WAIT(1); else CP_WAIT(0);
        __syncthreads();

        const uint32_t aKh = kvbase + (uint32_t)((cur * 4 + 0) * KV_E) * 2;
        const uint32_t aKl = kvbase + (uint32_t)((cur * 4 + 1) * KV_E) * 2;
        const uint32_t aVh = kvbase + (uint32_t)((cur * 4 + 2) * KV_E) * 2;
        const uint32_t aVl = kvbase + (uint32_t)((cur * 4 + 3) * KV_E) * 2;

        // S = Q K^T (3 split products)
        float sacc[8][4] = {};
        #pragma unroll
        for (int kk = 0; kk < 64; kk += 16) {
            uint32_t qh[4], ql[4], kh[4][4], kl[4][4];
            uint32_t offA = ((wm + a_row) * TSTR + kk + a_col) * 2;
            ldmx4(qh, aQh + offA);
            ldmx4(ql, aQl + offA);
            #pragma unroll
            for (int t = 0; t < 4; t++) {
                uint32_t offB = ((t * 16 + b_row) * TSTR + kk + b_col) * 2;
                ldmx4(kh[t], aKh + offB);
                ldmx4(kl[t], aKl + offB);
            }
            #pragma unroll
            for (int nj = 0; nj < 8; nj++) {
                const uint32_t* bh = &kh[nj >> 1][(nj & 1) * 2];
                const uint32_t* bl = &kl[nj >> 1][(nj & 1) * 2];
                mma16816(sacc[nj], qh, bh);
                mma16816(sacc[nj], qh, bl);
                mma16816(sacc[nj], ql, bh);
            }
        }

        // scale + bias + mask (bits)
        #pragma unroll
        for (int nj = 0; nj < 8; nj++) {
            int bi = (lane & 3) + nj * 4;
            sacc[nj][0] = ((mwA.x >> bi) & 1) ? fmaf(sacc[nj][0], 0.125f, bvA[nj].x) : -1e9f;
            sacc[nj][1] = ((mwA.y >> bi) & 1) ? fmaf(sacc[nj][1], 0.125f, bvA[nj].y) : -1e9f;
            sacc[nj][2] = ((mwB.x >> bi) & 1) ? fmaf(sacc[nj][2], 0.125f, bvB[nj].x) : -1e9f;
            sacc[nj][3] = ((mwB.y >> bi) & 1) ? fmaf(sacc[nj][3], 0.125f, bvB[nj].y) : -1e9f;
        }

        // online softmax
        float mx0 = -INFINITY, mx1 = -INFINITY;
        #pragma unroll
        for (int nj = 0; nj < 8; nj++) {
            mx0 = fmaxf(mx0, fmaxf(sacc[nj][0], sacc[nj][1]));
            mx1 = fmaxf(mx1, fmaxf(sacc[nj][2], sacc[nj][3]));
        }
        mx0 = fmaxf(mx0, __shfl_xor_sync(0xffffffffu, mx0, 1));
        mx0 = fmaxf(mx0, __shfl_xor_sync(0xffffffffu, mx0, 2));
        mx1 = fmaxf(mx1, __shfl_xor_sync(0xffffffffu, mx1, 1));
        mx1 = fmaxf(mx1, __shfl_xor_sync(0xffffffffu, mx1, 2));
        float mn0 = fmaxf(m0, mx0), mn1 = fmaxf(m1, mx1);
        float alpha0 = __expf(m0 - mn0), alpha1 = __expf(m1 - mn1);
        m0 = mn0; m1 = mn1;

        float ts0 = 0.f, ts1 = 0.f;
        uint32_t ph[8][2], pl[8][2];
        #pragma unroll
        for (int nj = 0; nj < 8; nj++) {
            float p0 = __expf(sacc[nj][0] - mn0);
            float p1 = __expf(sacc[nj][1] - mn0);
            float p2 = __expf(sacc[nj][2] - mn1);
            float p3 = __expf(sacc[nj][3] - mn1);
            ts0 += p0 + p1;
            ts1 += p2 + p3;
            float q0, q1, q2, q3;
            ph[nj][0] = pack_hi(p0, p1, q0, q1);
            ph[nj][1] = pack_hi(p2, p3, q2, q3);
            pl[nj][0] = pack_bf(q0, q1);
            pl[nj][1] = pack_bf(q2, q3);
        }
        ts0 += __shfl_xor_sync(0xffffffffu, ts0, 1);
        ts0 += __shfl_xor_sync(0xffffffffu, ts0, 2);
        ts1 += __shfl_xor_sync(0xffffffffu, ts1, 1);
        ts1 += __shfl_xor_sync(0xffffffffu, ts1, 2);
        l0 = l0 * alpha0 + ts0;
        l1 = l1 * alpha1 + ts1;

        #pragma unroll
        for (int nj = 0; nj < 8; nj++) {
            oacc[nj][0] *= alpha0; oacc[nj][1] *= alpha0;
            oacc[nj][2] *= alpha1; oacc[nj][3] *= alpha1;
        }

        // O += P @ V
        #pragma unroll
        for (int kk = 0; kk < 64; kk += 16) {
            int nt = kk >> 3;
            uint32_t aPh[4] = { ph[nt][0], ph[nt][1], ph[nt + 1][0], ph[nt + 1][1] };
            uint32_t aPl[4] = { pl[nt][0], pl[nt][1], pl[nt + 1][0], pl[nt + 1][1] };
            uint32_t vh[4][4], vl[4][4];
            #pragma unroll
            for (int t = 0; t < 4; t++) {
                uint32_t offV = ((t * 16 + b_row) * TSTR + kk + b_col) * 2;
                ldmx4(vh[t], aVh + offV);
                ldmx4(vl[t], aVl + offV);
            }
            #pragma unroll
            for (int nj = 0; nj < 8; nj++) {
                const uint32_t* bh = &vh[nj >> 1][(nj & 1) * 2];
                const uint32_t* bl = &vl[nj >> 1][(nj & 1) * 2];
                mma16816(oacc[nj], aPh, bh);
                mma16816(oacc[nj], aPh, bl);
                mma16816(oacc[nj], aPl, bh);
            }
        }
        __syncthreads();
    }

    // epilogue
    float inv0 = 1.0f / l0, inv1 = 1.0f / l1;
    int rowA = bb * S + qt * 128 + wm + r;
    #pragma unroll
    for (int nj = 0; nj < 8; nj++) {
        int col = h * DH + nj * 8 + qc;
        float q0, q1, q2, q3;
        uint32_t h01 = pack_hi(oacc[nj][0] * inv0, oacc[nj][1] * inv0, q0, q1);
        uint32_t h23 = pack_hi(oacc[nj][2] * inv1, oacc[nj][3] * inv1, q2, q3);
        *(uint32_t*)&Ah[(size_t)rowA * HID + col]       = h01;
        *(uint32_t*)&Al[(size_t)rowA * HID + col]       = pack_bf(q0, q1);
        *(uint32_t*)&Ah[(size_t)(rowA + 8) * HID + col] = h23;
        *(uint32_t*)&Al[(size_t)(rowA + 8) * HID + col] = pack_bf(q2, q3);
    }
}

// ---------------------------------------------------------------------------
extern "C" void kernel_launch(void* const* d_in, const int* in_sizes, int n_in,
                              void* d_out, int out_size)
{
    const float* X    = (const float*)d_in[0];
    const float* bias = (const float*)d_in[1];
    const int*   mask = (const int*  )d_in[2];
    const float* Wq   = (const float*)d_in[3];
    const float* Wk   = (const float*)d_in[4];
    const float* Wv   = (const float*)d_in[5];
    const float* Wo   = (const float*)d_in[6];
    float* out = (float*)d_out;

    __nv_bfloat16 *pXh, *pXl, *pQh, *pQl, *pKh, *pKl, *pVh, *pVl, *pVTh, *pVTl, *pAh, *pAl;
    __nv_bfloat16 *pWq, *pWq2, *pWk, *pWk2, *pWv, *pWv2, *pWo, *pWo2;
    cudaGetSymbolAddress((void**)&pXh, g_Xhi);   cudaGetSymbolAddress((void**)&pXl, g_Xlo);
    cudaGetSymbolAddress((void**)&pQh, g_Qh);    cudaGetSymbolAddress((void**)&pQl, g_Ql);
    cudaGetSymbolAddress((void**)&pKh, g_Kh);    cudaGetSymbolAddress((void**)&pKl, g_Kl);
    cudaGetSymbolAddress((void**)&pVh, g_Vh);    cudaGetSymbolAddress((void**)&pVl, g_Vl);
    cudaGetSymbolAddress((void**)&pVTh, g_VTh);  cudaGetSymbolAddress((void**)&pVTl, g_VTl);
    cudaGetSymbolAddress((void**)&pAh, g_Ah);    cudaGetSymbolAddress((void**)&pAl, g_Al);
    cudaGetSymbolAddress((void**)&pWq, g_WqThi); cudaGetSymbolAddress((void**)&pWq2, g_WqTlo);
    cudaGetSymbolAddress((void**)&pWk, g_WkThi); cudaGetSymbolAddress((void**)&pWk2, g_WkTlo);
    cudaGetSymbolAddress((void**)&pWv, g_WvThi); cudaGetSymbolAddress((void**)&pWv2, g_WvTlo);
    cudaGetSymbolAddress((void**)&pWo, g_WoThi); cudaGetSymbolAddress((void**)&pWo2, g_WoTlo);

    cudaFuncSetAttribute(gemm_mma, cudaFuncAttributeMaxDynamicSharedMemorySize, GEMM_SMEM);
    cudaFuncSetAttribute(attn_mma, cudaFuncAttributeMaxDynamicSharedMemorySize, ATTN_SMEM);

    // prep
    split_kernel<<<(B*S*HID/4 + 255)/256, 256>>>(X, pXh, pXl, B*S*HID/4);
    maskpack<<<B*S, 512>>>(mask);
    transpose_split<<<dim3((NH*DH)/32,  HID/32), dim3(32, 8)>>>(Wq, pWq, pWq2, HID, NH*DH);
    transpose_split<<<dim3((NKV*DH)/32, HID/32), dim3(32, 8)>>>(Wk, pWk, pWk2, HID, NKV*DH);
    transpose_split<<<dim3((NKV*DH)/32, HID/32), dim3(32, 8)>>>(Wv, pWv, pWv2, HID, NKV*DH);
    transpose_split<<<dim3(HID/32,      HID/32), dim3(32, 8)>>>(Wo, pWo, pWo2, HID, HID);

    // projections
    gemm_mma<<<dim3((NH*DH)/128,  (B*S)/128), 256, GEMM_SMEM>>>(pXh, pXl, pWq, pWq2, nullptr, pQh, pQl, B*S, NH*DH,  HID);
    gemm_mma<<<dim3((NKV*DH)/128, (B*S)/128), 256, GEMM_SMEM>>>(pXh, pXl, pWk, pWk2, nullptr, pKh, pKl, B*S, NKV*DH, HID);
    gemm_mma<<<dim3((NKV*DH)/128, (B*S)/128), 256, GEMM_SMEM>>>(pXh, pXl, pWv, pWv2, nullptr, pVh, pVl, B*S, NKV*DH, HID);
    vt_transpose<<<dim3(S/32, DH/32, B*NKV), dim3(32, 8)>>>(pVh, pVl, pVTh, pVTl);

    // attention
    attn_mma<<<dim3(S/128, NH, B), 256, ATTN_SMEM>>>(bias, pAh, pAl);

    // output projection
    gemm_mma<<<dim3(HID/128, (B*S)/128), 256, GEMM_SMEM>>>(pAh, pAl, pWo, pWo2, out, nullptr, nullptr, B*S, HID, HID);
}